// round 14
// baseline (speedup 1.0000x reference)
#include <cuda_runtime.h>
#include <cuda_bf16.h>
#include <cstdint>

// out[b,i,j] = Vx(i; t0,t2) * Vy(j; t1,t2), with
//   t = x @ (W1@W2) + (b1@W2 + b2)   (the two linears collapse)
// SINGLE fused kernel:
//   Blocks 0..D/8-1 first compute Weff[1024,3] (warp per d-row, W2 staged in
//   reused smem) + beff, publish via g_ready flag (threadfence + atomic).
//   All blocks spin (1 thread + nanosleep) until ready, then run the frozen
//   R10 boxcar (warp per row, float4 GEMV, STG.64.CS raster) reading weights
//   with __ldcg. Counters self-reset (last block out) for graph replays.

#define MAX_D 1024
#define MAX_H 512
#define S 56
#define KSTEEP 10.0f

__device__ float g_w0[MAX_D];
__device__ float g_w1[MAX_D];
__device__ float g_w2[MAX_D];
__device__ float g_beff[3];
__device__ unsigned g_ready;   // # weff blocks finished (self-resetting)
__device__ unsigned g_done;    // # blocks finished     (self-resetting)

__device__ __forceinline__ float fsigmoid(float z) {
    return 1.0f / (1.0f + __expf(-z));
}

__global__ __launch_bounds__(256) void fused_kernel(
        const float* __restrict__ x,
        const float* __restrict__ W1,
        const float* __restrict__ b1,
        const float* __restrict__ W2,
        const float* __restrict__ b2,
        float* __restrict__ out,
        int B, int D, int H, int nweff) {
    // 12KB: boxcar weights; weff phase reuses the front as its W2 stage.
    __shared__ __align__(16) float s_mem[3 * MAX_D];
    float* s_w0 = s_mem;
    float* s_w1 = s_mem + MAX_D;
    float* s_w2 = s_mem + 2 * MAX_D;

    const int tid  = threadIdx.x;
    const int lane = tid & 31;
    const int wid  = tid >> 5;

    // ================= Phase 0: weff (blocks 0..nweff-1) =================
    if ((int)blockIdx.x < nweff) {
        float* s_W2 = s_mem;                    // 1536 floats, reused space
        {
            const float4* __restrict__ W24 = (const float4*)W2;
            float4* __restrict__ s4 = (float4*)s_W2;
            const int n4 = (H * 3) >> 2;
            for (int idx = tid; idx < n4; idx += blockDim.x)
                s4[idx] = W24[idx];
        }
        __syncthreads();

        const int drow = blockIdx.x * 8 + wid;  // warp per d-row
        if (drow < D) {
            const float4* __restrict__ row4 = (const float4*)(W1 + (size_t)drow * H);
            const int nch = H >> 2;             // 128 for H=512
            float a0 = 0.f, a1 = 0.f, a2 = 0.f;
            #pragma unroll 4
            for (int c = lane; c < nch; c += 32) {
                float4 w = __ldcs(&row4[c]);
                int h = c << 2;
                a0 = fmaf(w.x, s_W2[(h+0)*3+0], fmaf(w.y, s_W2[(h+1)*3+0],
                     fmaf(w.z, s_W2[(h+2)*3+0], fmaf(w.w, s_W2[(h+3)*3+0], a0))));
                a1 = fmaf(w.x, s_W2[(h+0)*3+1], fmaf(w.y, s_W2[(h+1)*3+1],
                     fmaf(w.z, s_W2[(h+2)*3+1], fmaf(w.w, s_W2[(h+3)*3+1], a1))));
                a2 = fmaf(w.x, s_W2[(h+0)*3+2], fmaf(w.y, s_W2[(h+1)*3+2],
                     fmaf(w.z, s_W2[(h+2)*3+2], fmaf(w.w, s_W2[(h+3)*3+2], a2))));
            }
            #pragma unroll
            for (int o = 16; o > 0; o >>= 1) {
                a0 += __shfl_xor_sync(0xffffffffu, a0, o);
                a1 += __shfl_xor_sync(0xffffffffu, a1, o);
                a2 += __shfl_xor_sync(0xffffffffu, a2, o);
            }
            if (lane == 0) {
                g_w0[drow] = a0;
                g_w1[drow] = a1;
                g_w2[drow] = a2;
            }
        }

        // beff: block 0, warp 0 (after its weff row)
        if (blockIdx.x == 0 && wid == 0) {
            float s0 = 0.f, s1 = 0.f, s2 = 0.f;
            for (int h = lane; h < H; h += 32) {
                float bv = b1[h];
                s0 = fmaf(bv, s_W2[h * 3 + 0], s0);
                s1 = fmaf(bv, s_W2[h * 3 + 1], s1);
                s2 = fmaf(bv, s_W2[h * 3 + 2], s2);
            }
            #pragma unroll
            for (int o = 16; o > 0; o >>= 1) {
                s0 += __shfl_xor_sync(0xffffffffu, s0, o);
                s1 += __shfl_xor_sync(0xffffffffu, s1, o);
                s2 += __shfl_xor_sync(0xffffffffu, s2, o);
            }
            if (lane == 0) {
                g_beff[0] = s0 + b2[0];
                g_beff[1] = s1 + b2[1];
                g_beff[2] = s2 + b2[2];
            }
        }

        __threadfence();                        // publish g_w*/g_beff
        __syncthreads();
        if (tid == 0) atomicAdd(&g_ready, 1u);
    }

    // ================= Barrier: wait for all weff blocks =================
    if (tid == 0) {
        while (atomicAdd(&g_ready, 0u) < (unsigned)nweff)
            __nanosleep(64);
        __threadfence();                        // acquire
    }
    __syncthreads();

    // ================= Phase 1: boxcar (frozen R10 body) =================
    // weight fill via __ldcg (L2-coherent; overwrites the W2 stage area)
    for (int e = tid; e < D; e += blockDim.x) {
        s_w0[e] = __ldcg(&g_w0[e]);
        s_w1[e] = __ldcg(&g_w1[e]);
        s_w2[e] = __ldcg(&g_w2[e]);
    }
    const float be0 = __ldcg(&g_beff[0]);
    const float be1 = __ldcg(&g_beff[1]);
    const float be2 = __ldcg(&g_beff[2]);
    __syncthreads();

    const int row = blockIdx.x * (blockDim.x >> 5) + wid;
    if (row < B) {
        // ---- skinny GEMV, float4: 8 LDG.128 + 24 LDS.128 per lane ----
        const float4* __restrict__ x4 = (const float4*)(x + (size_t)row * D);
        const int nch = D >> 2;                 // 256 for D=1024
        float a0 = 0.f, a1 = 0.f, a2 = 0.f;
        #pragma unroll 4
        for (int c = lane; c < nch; c += 32) {
            float4 xv = __ldcs(&x4[c]);
            int e = c << 2;
            float4 w0 = *(const float4*)&s_w0[e];
            float4 w1 = *(const float4*)&s_w1[e];
            float4 w2 = *(const float4*)&s_w2[e];
            a0 = fmaf(xv.x, w0.x, fmaf(xv.y, w0.y, fmaf(xv.z, w0.z, fmaf(xv.w, w0.w, a0))));
            a1 = fmaf(xv.x, w1.x, fmaf(xv.y, w1.y, fmaf(xv.z, w1.z, fmaf(xv.w, w1.w, a1))));
            a2 = fmaf(xv.x, w2.x, fmaf(xv.y, w2.y, fmaf(xv.z, w2.z, fmaf(xv.w, w2.w, a2))));
        }
        #pragma unroll
        for (int o = 16; o > 0; o >>= 1) {
            a0 += __shfl_xor_sync(0xffffffffu, a0, o);
            a1 += __shfl_xor_sync(0xffffffffu, a1, o);
            a2 += __shfl_xor_sync(0xffffffffu, a2, o);
        }
        const float t0 = a0 + be0;   // x center (maps to i)
        const float t1 = a1 + be1;   // y center (maps to j)
        const float t2 = a2 + be2;   // size

        // ---- boxcar profiles: lane covers coords lane and lane+32 ----
        const float half = 0.5f * t2;
        const float c0 = (float)lane;
        const float c1 = (float)(lane + 32);

        float vx0 = fsigmoid(KSTEEP * (c0 - t0 + half)) - fsigmoid(KSTEEP * (c0 - t0 - half));
        float vy0 = fsigmoid(KSTEEP * (c0 - t1 + half)) - fsigmoid(KSTEEP * (c0 - t1 - half));
        float vx1 = 0.f, vy1 = 0.f;
        if (lane < S - 32) {
            vx1 = fsigmoid(KSTEEP * (c1 - t0 + half)) - fsigmoid(KSTEEP * (c1 - t0 - half));
            vy1 = fsigmoid(KSTEEP * (c1 - t1 + half)) - fsigmoid(KSTEEP * (c1 - t1 - half));
        }

        // ---- gather vy pair: vy[2*lane], vy[2*lane+1] (lanes 0-27) ----
        const int e_idx = 2 * lane;
        const int o_idx = 2 * lane + 1;
        float eA = __shfl_sync(0xffffffffu, vy0, e_idx & 31);
        float eB = __shfl_sync(0xffffffffu, vy1, e_idx & 31);
        float oA = __shfl_sync(0xffffffffu, vy0, o_idx & 31);
        float oB = __shfl_sync(0xffffffffu, vy1, o_idx & 31);
        const float vyA = (e_idx < 32) ? eA : eB;
        const float vyB = (o_idx < 32) ? oA : oB;

        // ---- rasterize: one STG.64.CS per output row (lanes 0-27) ----
        float2* __restrict__ o2 = (float2*)(out + (size_t)row * (S * S));
        #pragma unroll
        for (int i = 0; i < S; i++) {
            float src = (i < 32) ? vx0 : vx1;
            float vxi = __shfl_sync(0xffffffffu, src, i & 31);
            if (lane < S / 2) {
                float2 r;
                r.x = vxi * vyA;
                r.y = vxi * vyB;
                __stcs(&o2[lane], r);
            }
            o2 += S / 2;
        }
    }

    // ============ Self-reset for graph replay (last block out) ============
    if (tid == 0) {
        unsigned d = atomicAdd(&g_done, 1u);
        if (d == gridDim.x - 1) {               // everyone has passed the spin
            g_ready = 0u;
            g_done  = 0u;
            __threadfence();
        }
    }
}

// ---------------------------------------------------------------------------
// Launch. Inputs: x[B,D], W1[D,H], b1[H], W2[H,3], b2[3]. Output: [B,56,56] f32.
// ---------------------------------------------------------------------------
extern "C" void kernel_launch(void* const* d_in, const int* in_sizes, int n_in,
                              void* d_out, int out_size) {
    const float* x  = (const float*)d_in[0];
    const float* W1 = (const float*)d_in[1];
    const float* b1 = (const float*)d_in[2];
    const float* W2 = (const float*)d_in[3];
    const float* b2 = (const float*)d_in[4];
    float* out = (float*)d_out;

    const int H = in_sizes[2];           // 512
    const int D = in_sizes[1] / H;       // 1024
    const int B = in_sizes[0] / D;       // 16384

    const int threads = 256;
    const int rows_per_block = threads / 32;                 // 8
    int blocks = (B + rows_per_block - 1) / rows_per_block;  // 2048
    int nweff  = (D + rows_per_block - 1) / rows_per_block;  // 128
    if (blocks < nweff) blocks = nweff;                      // safety

    fused_kernel<<<blocks, threads>>>(x, W1, b1, W2, b2, out, B, D, H, nweff);
}

// round 15
// speedup vs baseline: 1.0283x; 1.0283x over previous
#include <cuda_runtime.h>
#include <cuda_bf16.h>
#include <cstdint>

// out[b,i,j] = Vx(i; t0,t2) * Vy(j; t1,t2), with
//   t = x @ (W1@W2) + (b1@W2 + b2)   (the two linears collapse)
// Structure = proven R10 (best: 51.7us). Single change: output stores use
// __stwt (write-through) to bypass the L2 dirty-eviction machinery -- the
// last untested hardware path on the 4.5TB/s write-bandwidth plateau.

#define MAX_D 1024
#define MAX_H 512
#define S 56
#define KSTEEP 10.0f

__device__ float g_w0[MAX_D];
__device__ float g_w1[MAX_D];
__device__ float g_w2[MAX_D];
__device__ float g_beff[3];

// ---------------------------------------------------------------------------
// Kernel A: Weff = W1 @ W2 (warp per d-row, W2 staged in smem),
//           beff = b1 @ W2 + b2 (one warp in block 0).
// ---------------------------------------------------------------------------
__global__ __launch_bounds__(256) void weff_kernel(const float* __restrict__ W1,
                                                   const float* __restrict__ b1,
                                                   const float* __restrict__ W2,
                                                   const float* __restrict__ b2,
                                                   int D, int H) {
    __shared__ __align__(16) float s_W2[MAX_H * 3];

    {
        const float4* __restrict__ W24 = (const float4*)W2;
        float4* __restrict__ s4 = (float4*)s_W2;
        const int n4 = (H * 3) >> 2;
        for (int idx = threadIdx.x; idx < n4; idx += blockDim.x)
            s4[idx] = W24[idx];
    }
    __syncthreads();

    const int lane = threadIdx.x & 31;
    const int warp = (blockIdx.x * blockDim.x + threadIdx.x) >> 5;

    if (warp < D) {
        const float4* __restrict__ row4 = (const float4*)(W1 + (size_t)warp * H);
        const int nch = H >> 2;                 // 128 for H=512
        float a0 = 0.f, a1 = 0.f, a2 = 0.f;
        #pragma unroll 4
        for (int c = lane; c < nch; c += 32) {
            float4 w = __ldcs(&row4[c]);        // streaming LDG.128
            int h = c << 2;
            a0 = fmaf(w.x, s_W2[(h+0)*3+0], fmaf(w.y, s_W2[(h+1)*3+0],
                 fmaf(w.z, s_W2[(h+2)*3+0], fmaf(w.w, s_W2[(h+3)*3+0], a0))));
            a1 = fmaf(w.x, s_W2[(h+0)*3+1], fmaf(w.y, s_W2[(h+1)*3+1],
                 fmaf(w.z, s_W2[(h+2)*3+1], fmaf(w.w, s_W2[(h+3)*3+1], a1))));
            a2 = fmaf(w.x, s_W2[(h+0)*3+2], fmaf(w.y, s_W2[(h+1)*3+2],
                 fmaf(w.z, s_W2[(h+2)*3+2], fmaf(w.w, s_W2[(h+3)*3+2], a2))));
        }
        #pragma unroll
        for (int o = 16; o > 0; o >>= 1) {
            a0 += __shfl_xor_sync(0xffffffffu, a0, o);
            a1 += __shfl_xor_sync(0xffffffffu, a1, o);
            a2 += __shfl_xor_sync(0xffffffffu, a2, o);
        }
        if (lane == 0) {
            g_w0[warp] = a0;
            g_w1[warp] = a1;
            g_w2[warp] = a2;
        }
    }

    if (blockIdx.x == 0 && threadIdx.x < 32) {
        float s0 = 0.f, s1 = 0.f, s2 = 0.f;
        for (int h = lane; h < H; h += 32) {
            float bv = b1[h];
            s0 = fmaf(bv, s_W2[h * 3 + 0], s0);
            s1 = fmaf(bv, s_W2[h * 3 + 1], s1);
            s2 = fmaf(bv, s_W2[h * 3 + 2], s2);
        }
        #pragma unroll
        for (int o = 16; o > 0; o >>= 1) {
            s0 += __shfl_xor_sync(0xffffffffu, s0, o);
            s1 += __shfl_xor_sync(0xffffffffu, s1, o);
            s2 += __shfl_xor_sync(0xffffffffu, s2, o);
        }
        if (lane == 0) {
            g_beff[0] = s0 + b2[0];
            g_beff[1] = s1 + b2[1];
            g_beff[2] = s2 + b2[2];
        }
    }
}

// ---------------------------------------------------------------------------
// Kernel B: one warp per batch row (frozen R10 structure, __stwt stores).
// ---------------------------------------------------------------------------
__device__ __forceinline__ float fsigmoid(float z) {
    return 1.0f / (1.0f + __expf(-z));
}

__global__ __launch_bounds__(256) void boxcar_kernel(const float* __restrict__ x,
                                                     float* __restrict__ out,
                                                     int B, int D) {
    __shared__ __align__(16) float s_w0[MAX_D];
    __shared__ __align__(16) float s_w1[MAX_D];
    __shared__ __align__(16) float s_w2[MAX_D];

    for (int e = threadIdx.x; e < D; e += blockDim.x) {
        s_w0[e] = g_w0[e];
        s_w1[e] = g_w1[e];
        s_w2[e] = g_w2[e];
    }
    __syncthreads();

    const int lane = threadIdx.x & 31;
    const int wid  = threadIdx.x >> 5;
    const int row  = blockIdx.x * (blockDim.x >> 5) + wid;
    if (row >= B) return;

    // ---- skinny GEMV, float4-vectorized: 8 LDG.128 + 24 LDS.128 per lane ----
    const float4* __restrict__ x4 = (const float4*)(x + (size_t)row * D);
    const int nch = D >> 2;                     // 256 for D=1024
    float a0 = 0.f, a1 = 0.f, a2 = 0.f;
    #pragma unroll 4
    for (int c = lane; c < nch; c += 32) {
        float4 xv = __ldcs(&x4[c]);             // streaming LDG.128
        int e = c << 2;
        float4 w0 = *(const float4*)&s_w0[e];
        float4 w1 = *(const float4*)&s_w1[e];
        float4 w2 = *(const float4*)&s_w2[e];
        a0 = fmaf(xv.x, w0.x, fmaf(xv.y, w0.y, fmaf(xv.z, w0.z, fmaf(xv.w, w0.w, a0))));
        a1 = fmaf(xv.x, w1.x, fmaf(xv.y, w1.y, fmaf(xv.z, w1.z, fmaf(xv.w, w1.w, a1))));
        a2 = fmaf(xv.x, w2.x, fmaf(xv.y, w2.y, fmaf(xv.z, w2.z, fmaf(xv.w, w2.w, a2))));
    }
    #pragma unroll
    for (int o = 16; o > 0; o >>= 1) {
        a0 += __shfl_xor_sync(0xffffffffu, a0, o);
        a1 += __shfl_xor_sync(0xffffffffu, a1, o);
        a2 += __shfl_xor_sync(0xffffffffu, a2, o);
    }
    const float t0 = a0 + g_beff[0];   // x center (maps to i)
    const float t1 = a1 + g_beff[1];   // y center (maps to j)
    const float t2 = a2 + g_beff[2];   // size

    // ---- boxcar profiles: lane covers coords lane and lane+32 ----
    const float half = 0.5f * t2;
    const float c0 = (float)lane;
    const float c1 = (float)(lane + 32);

    float vx0 = fsigmoid(KSTEEP * (c0 - t0 + half)) - fsigmoid(KSTEEP * (c0 - t0 - half));
    float vy0 = fsigmoid(KSTEEP * (c0 - t1 + half)) - fsigmoid(KSTEEP * (c0 - t1 - half));
    float vx1 = 0.f, vy1 = 0.f;
    if (lane < S - 32) {
        vx1 = fsigmoid(KSTEEP * (c1 - t0 + half)) - fsigmoid(KSTEEP * (c1 - t0 - half));
        vy1 = fsigmoid(KSTEEP * (c1 - t1 + half)) - fsigmoid(KSTEEP * (c1 - t1 - half));
    }

    // ---- gather vy pair for this lane: vy[2*lane], vy[2*lane+1] (lanes 0-27) ----
    const int e_idx = 2 * lane;
    const int o_idx = 2 * lane + 1;
    float eA = __shfl_sync(0xffffffffu, vy0, e_idx & 31);
    float eB = __shfl_sync(0xffffffffu, vy1, e_idx & 31);
    float oA = __shfl_sync(0xffffffffu, vy0, o_idx & 31);
    float oB = __shfl_sync(0xffffffffu, vy1, o_idx & 31);
    const float vyA = (e_idx < 32) ? eA : eB;
    const float vyB = (o_idx < 32) ? oA : oB;

    // ---- rasterize: one STG.64.WT per output row (lanes 0-27) ----
    float2* __restrict__ o2 = (float2*)(out + (size_t)row * (S * S));
    #pragma unroll
    for (int i = 0; i < S; i++) {
        float src = (i < 32) ? vx0 : vx1;
        float vxi = __shfl_sync(0xffffffffu, src, i & 31);
        if (lane < S / 2) {
            float2 r;
            r.x = vxi * vyA;
            r.y = vxi * vyB;
            __stwt(&o2[lane], r);               // write-through: bypass L2
        }                                       // dirty-eviction machinery
        o2 += S / 2;
    }
}

// ---------------------------------------------------------------------------
// Launch. Inputs: x[B,D], W1[D,H], b1[H], W2[H,3], b2[3]. Output: [B,56,56] f32.
// ---------------------------------------------------------------------------
extern "C" void kernel_launch(void* const* d_in, const int* in_sizes, int n_in,
                              void* d_out, int out_size) {
    const float* x  = (const float*)d_in[0];
    const float* W1 = (const float*)d_in[1];
    const float* b1 = (const float*)d_in[2];
    const float* W2 = (const float*)d_in[3];
    const float* b2 = (const float*)d_in[4];
    float* out = (float*)d_out;

    const int H = in_sizes[2];           // 512
    const int D = in_sizes[1] / H;       // 1024
    const int B = in_sizes[0] / D;       // 16384

    {
        int threads = 256;
        int blocks = (D * 32 + threads - 1) / threads;   // warp per d-row
        weff_kernel<<<blocks, threads>>>(W1, b1, W2, b2, D, H);
    }
    {
        int threads = 256;
        int rows_per_block = threads / 32;
        int blocks = (B + rows_per_block - 1) / rows_per_block;
        boxcar_kernel<<<blocks, threads>>>(x, out, B, D);
    }
}

// round 16
// speedup vs baseline: 1.0907x; 1.0607x over previous
#include <cuda_runtime.h>
#include <cuda_bf16.h>
#include <cstdint>

// out[b,i,j] = Vx(i; t0,t2) * Vy(j; t1,t2), with
//   t = x @ (W1@W2) + (b1@W2 + b2)   (the two linears collapse)
// FINAL (= R10, session best 51.7us):
//   Kernel A: Weff[1024,3] + beff[3], W2 staged in smem, float4 W1 reads.
//   Kernel B: warp per batch row, float4 GEMV (__ldcs), boxcar profiles via
//     MUFU sigmoid, raster = one STG.64.CS per output row.
//   Boxcar measured at ~96% of the HBM write-path ceiling (4.56 TB/s on a
//   pure 205MB store stream); probes (STG.32/128, WT, flat order, persistent,
//   PDL, fusion, K-split) all neutral or regressive.

#define MAX_D 1024
#define MAX_H 512
#define S 56
#define KSTEEP 10.0f

__device__ float g_w0[MAX_D];
__device__ float g_w1[MAX_D];
__device__ float g_w2[MAX_D];
__device__ float g_beff[3];

// ---------------------------------------------------------------------------
// Kernel A: Weff = W1 @ W2 (warp per d-row, W2 staged in smem),
//           beff = b1 @ W2 + b2 (one warp in block 0).
// ---------------------------------------------------------------------------
__global__ __launch_bounds__(256) void weff_kernel(const float* __restrict__ W1,
                                                   const float* __restrict__ b1,
                                                   const float* __restrict__ W2,
                                                   const float* __restrict__ b2,
                                                   int D, int H) {
    __shared__ __align__(16) float s_W2[MAX_H * 3];

    {
        const float4* __restrict__ W24 = (const float4*)W2;
        float4* __restrict__ s4 = (float4*)s_W2;
        const int n4 = (H * 3) >> 2;
        for (int idx = threadIdx.x; idx < n4; idx += blockDim.x)
            s4[idx] = W24[idx];
    }
    __syncthreads();

    const int lane = threadIdx.x & 31;
    const int warp = (blockIdx.x * blockDim.x + threadIdx.x) >> 5;

    if (warp < D) {
        const float4* __restrict__ row4 = (const float4*)(W1 + (size_t)warp * H);
        const int nch = H >> 2;                 // 128 for H=512
        float a0 = 0.f, a1 = 0.f, a2 = 0.f;
        #pragma unroll 4
        for (int c = lane; c < nch; c += 32) {
            float4 w = __ldcs(&row4[c]);        // streaming LDG.128
            int h = c << 2;
            a0 = fmaf(w.x, s_W2[(h+0)*3+0], fmaf(w.y, s_W2[(h+1)*3+0],
                 fmaf(w.z, s_W2[(h+2)*3+0], fmaf(w.w, s_W2[(h+3)*3+0], a0))));
            a1 = fmaf(w.x, s_W2[(h+0)*3+1], fmaf(w.y, s_W2[(h+1)*3+1],
                 fmaf(w.z, s_W2[(h+2)*3+1], fmaf(w.w, s_W2[(h+3)*3+1], a1))));
            a2 = fmaf(w.x, s_W2[(h+0)*3+2], fmaf(w.y, s_W2[(h+1)*3+2],
                 fmaf(w.z, s_W2[(h+2)*3+2], fmaf(w.w, s_W2[(h+3)*3+2], a2))));
        }
        #pragma unroll
        for (int o = 16; o > 0; o >>= 1) {
            a0 += __shfl_xor_sync(0xffffffffu, a0, o);
            a1 += __shfl_xor_sync(0xffffffffu, a1, o);
            a2 += __shfl_xor_sync(0xffffffffu, a2, o);
        }
        if (lane == 0) {
            g_w0[warp] = a0;
            g_w1[warp] = a1;
            g_w2[warp] = a2;
        }
    }

    if (blockIdx.x == 0 && threadIdx.x < 32) {
        float s0 = 0.f, s1 = 0.f, s2 = 0.f;
        for (int h = lane; h < H; h += 32) {
            float bv = b1[h];
            s0 = fmaf(bv, s_W2[h * 3 + 0], s0);
            s1 = fmaf(bv, s_W2[h * 3 + 1], s1);
            s2 = fmaf(bv, s_W2[h * 3 + 2], s2);
        }
        #pragma unroll
        for (int o = 16; o > 0; o >>= 1) {
            s0 += __shfl_xor_sync(0xffffffffu, s0, o);
            s1 += __shfl_xor_sync(0xffffffffu, s1, o);
            s2 += __shfl_xor_sync(0xffffffffu, s2, o);
        }
        if (lane == 0) {
            g_beff[0] = s0 + b2[0];
            g_beff[1] = s1 + b2[1];
            g_beff[2] = s2 + b2[2];
        }
    }
}

// ---------------------------------------------------------------------------
// Kernel B: one warp per batch row.
// ---------------------------------------------------------------------------
__device__ __forceinline__ float fsigmoid(float z) {
    return 1.0f / (1.0f + __expf(-z));
}

__global__ __launch_bounds__(256) void boxcar_kernel(const float* __restrict__ x,
                                                     float* __restrict__ out,
                                                     int B, int D) {
    __shared__ __align__(16) float s_w0[MAX_D];
    __shared__ __align__(16) float s_w1[MAX_D];
    __shared__ __align__(16) float s_w2[MAX_D];

    for (int e = threadIdx.x; e < D; e += blockDim.x) {
        s_w0[e] = g_w0[e];
        s_w1[e] = g_w1[e];
        s_w2[e] = g_w2[e];
    }
    __syncthreads();

    const int lane = threadIdx.x & 31;
    const int wid  = threadIdx.x >> 5;
    const int row  = blockIdx.x * (blockDim.x >> 5) + wid;
    if (row >= B) return;

    // ---- skinny GEMV, float4-vectorized: 8 LDG.128 + 24 LDS.128 per lane ----
    const float4* __restrict__ x4 = (const float4*)(x + (size_t)row * D);
    const int nch = D >> 2;                     // 256 for D=1024
    float a0 = 0.f, a1 = 0.f, a2 = 0.f;
    #pragma unroll 4
    for (int c = lane; c < nch; c += 32) {
        float4 xv = __ldcs(&x4[c]);             // streaming LDG.128
        int e = c << 2;
        float4 w0 = *(const float4*)&s_w0[e];
        float4 w1 = *(const float4*)&s_w1[e];
        float4 w2 = *(const float4*)&s_w2[e];
        a0 = fmaf(xv.x, w0.x, fmaf(xv.y, w0.y, fmaf(xv.z, w0.z, fmaf(xv.w, w0.w, a0))));
        a1 = fmaf(xv.x, w1.x, fmaf(xv.y, w1.y, fmaf(xv.z, w1.z, fmaf(xv.w, w1.w, a1))));
        a2 = fmaf(xv.x, w2.x, fmaf(xv.y, w2.y, fmaf(xv.z, w2.z, fmaf(xv.w, w2.w, a2))));
    }
    #pragma unroll
    for (int o = 16; o > 0; o >>= 1) {
        a0 += __shfl_xor_sync(0xffffffffu, a0, o);
        a1 += __shfl_xor_sync(0xffffffffu, a1, o);
        a2 += __shfl_xor_sync(0xffffffffu, a2, o);
    }
    const float t0 = a0 + g_beff[0];   // x center (maps to i)
    const float t1 = a1 + g_beff[1];   // y center (maps to j)
    const float t2 = a2 + g_beff[2];   // size

    // ---- boxcar profiles: lane covers coords lane and lane+32 ----
    const float half = 0.5f * t2;
    const float c0 = (float)lane;
    const float c1 = (float)(lane + 32);

    float vx0 = fsigmoid(KSTEEP * (c0 - t0 + half)) - fsigmoid(KSTEEP * (c0 - t0 - half));
    float vy0 = fsigmoid(KSTEEP * (c0 - t1 + half)) - fsigmoid(KSTEEP * (c0 - t1 - half));
    float vx1 = 0.f, vy1 = 0.f;
    if (lane < S - 32) {
        vx1 = fsigmoid(KSTEEP * (c1 - t0 + half)) - fsigmoid(KSTEEP * (c1 - t0 - half));
        vy1 = fsigmoid(KSTEEP * (c1 - t1 + half)) - fsigmoid(KSTEEP * (c1 - t1 - half));
    }

    // ---- gather vy pair for this lane: vy[2*lane], vy[2*lane+1] (lanes 0-27) ----
    const int e_idx = 2 * lane;
    const int o_idx = 2 * lane + 1;
    float eA = __shfl_sync(0xffffffffu, vy0, e_idx & 31);
    float eB = __shfl_sync(0xffffffffu, vy1, e_idx & 31);
    float oA = __shfl_sync(0xffffffffu, vy0, o_idx & 31);
    float oB = __shfl_sync(0xffffffffu, vy1, o_idx & 31);
    const float vyA = (e_idx < 32) ? eA : eB;
    const float vyB = (o_idx < 32) ? oA : oB;

    // ---- rasterize: one STG.64.CS per output row (lanes 0-27) ----
    float2* __restrict__ o2 = (float2*)(out + (size_t)row * (S * S));
    #pragma unroll
    for (int i = 0; i < S; i++) {
        float src = (i < 32) ? vx0 : vx1;
        float vxi = __shfl_sync(0xffffffffu, src, i & 31);
        if (lane < S / 2) {
            float2 r;
            r.x = vxi * vyA;
            r.y = vxi * vyB;
            __stcs(&o2[lane], r);               // evict-first: best measured
        }
        o2 += S / 2;
    }
}

// ---------------------------------------------------------------------------
// Launch. Inputs: x[B,D], W1[D,H], b1[H], W2[H,3], b2[3]. Output: [B,56,56] f32.
// ---------------------------------------------------------------------------
extern "C" void kernel_launch(void* const* d_in, const int* in_sizes, int n_in,
                              void* d_out, int out_size) {
    const float* x  = (const float*)d_in[0];
    const float* W1 = (const float*)d_in[1];
    const float* b1 = (const float*)d_in[2];
    const float* W2 = (const float*)d_in[3];
    const float* b2 = (const float*)d_in[4];
    float* out = (float*)d_out;

    const int H = in_sizes[2];           // 512
    const int D = in_sizes[1] / H;       // 1024
    const int B = in_sizes[0] / D;       // 16384

    {
        int threads = 256;
        int blocks = (D * 32 + threads - 1) / threads;   // warp per d-row
        weff_kernel<<<blocks, threads>>>(W1, b1, W2, b2, D, H);
    }
    {
        int threads = 256;
        int rows_per_block = threads / 32;
        int blocks = (B + rows_per_block - 1) / rows_per_block;
        boxcar_kernel<<<blocks, threads>>>(x, out, B, D);
    }
}